// round 5
// baseline (speedup 1.0000x reference)
#include <cuda_runtime.h>

// Problem constants
#define B_DIM 128
#define T_DIM 256
#define D_DIM 32
#define N_DIM 64

// Scratch (device globals: no allocation allowed)
__device__ float g_aBuf[D_DIM * T_DIM * B_DIM];   // [i][t][b] unnormalized alphas
__device__ float g_denBuf[D_DIM * B_DIM];         // [i][b]
__device__ float g_gBuf[B_DIM * D_DIM * N_DIM];   // [b][i][k] g_n (normalized)
__device__ float g_hTBuf[B_DIM * D_DIM * N_DIM];  // [b][i][k] h_T

// ---------------- math helpers ----------------
static __device__ __forceinline__ float fsig(float x) {
    return __fdividef(1.0f, 1.0f + __expf(-x));
}
static __device__ __forceinline__ float ftanh_(float x) {
    float ax = fabsf(x);
    float e = __expf(-2.0f * ax);
    float t = 1.0f - __fdividef(2.0f * e, 1.0f + e);
    return copysignf(t, x);
}
// packed f32x2 fma (Blackwell)
static __device__ __forceinline__ void fma2(unsigned long long& a,
                                            unsigned long long b,
                                            unsigned long long c) {
    asm("fma.rn.f32x2 %0, %1, %2, %0;" : "+l"(a) : "l"(b), "l"(c));
}
static __device__ __forceinline__ unsigned long long pack2(float x) {
    unsigned long long r;
    asm("mov.b64 %0, {%1, %1};" : "=l"(r) : "f"(x));
    return r;
}
static __device__ __forceinline__ unsigned long long packab(float x, float y) {
    unsigned long long r;
    asm("mov.b64 %0, {%1, %2};" : "=l"(r) : "f"(x), "f"(y));
    return r;
}
static __device__ __forceinline__ float2 unpack2(unsigned long long a) {
    float lo, hi;
    asm("mov.b64 {%0, %1}, %2;" : "=f"(lo), "=f"(hi) : "l"(a));
    return make_float2(lo, hi);
}

// ---------------- shared memory layout (float offsets) ----------------
// W' interleaved: [j][kpair(32)][gate(4)][kappa(2)] -> row j = 256 floats = 64 ull2
#define SMW 0          // 64 j * 256 = 16384 floats
#define SMX 16384      // x: 256 t * 32 b = 8192
#define SMH 24576      // h ping-pong: 2 * (64 j * 32 b) = 4096
#define SMS 28672      // sp ping-pong: 2 * (16 w * 32 b) = 1024
#define SMTOT 29696    // floats -> 118784 bytes

// ===================== Kernel 1: fused LSTM + streamed attention =====================
// grid = (32 i, 4 b-chunks), block = 512 = 16 warps (4 per SMSP).
// warp w owns k in [4w, 4w+4); lane = bq*2 + p: p -> k-pair (k0 = 4w+2p), bq -> b-pair.
__global__ void __launch_bounds__(512, 1)
lstm_kernel(const float* __restrict__ x,
            const float* __restrict__ Uj, const float* __restrict__ Ui_,
            const float* __restrict__ Uf, const float* __restrict__ Uo,
            const float* __restrict__ Wj, const float* __restrict__ Wi_,
            const float* __restrict__ Wf, const float* __restrict__ Wo,
            const float* __restrict__ bj, const float* __restrict__ bi_,
            const float* __restrict__ bf, const float* __restrict__ bo,
            const float* __restrict__ Fa, const float* __restrict__ Fab) {
    extern __shared__ float sm[];
    const int tid  = threadIdx.x;
    const int w    = tid >> 5;
    const int lane = tid & 31;
    const int p    = lane & 1;
    const int bq   = lane >> 1;
    const int i    = blockIdx.x;
    const int b0   = blockIdx.y << 5;
    const int k0   = w * 4 + p * 2;        // first k of this thread's pair
    const int wq   = w * 4 + p * 2;        // ull2 base offset within row j (== 2*kpair)

    // ---- cooperative loads ----
    {
        const float* Wg[4] = {Wj, Wi_, Wf, Wo};
#pragma unroll
        for (int gg = 0; gg < 4; gg++) {
            const float* src = Wg[gg];
            for (int idx = tid; idx < 4096; idx += 512) {
                int j = idx >> 6, k = idx & 63;
                // W'[j][k>>1][g][k&1]
                sm[SMW + j * 256 + (k >> 1) * 8 + gg * 2 + (k & 1)] =
                    src[(j * 32 + i) * 64 + k];
            }
        }
        for (int idx = tid; idx < 8192; idx += 512) {
            int t = idx >> 5, bl = idx & 31;
            sm[SMX + idx] = x[((b0 + bl) * 256 + t) * 32 + i];
        }
        for (int idx = tid; idx < 4096; idx += 512) sm[SMH + idx] = 0.0f;
    }
    __syncthreads();

    // ---- per-thread constants (registers) ----
    unsigned long long bias2[4], u2[4];
    {
        const float* Bg[4] = {bj, bi_, bf, bo};
        const float* Ug[4] = {Uj, Ui_, Uf, Uo};
#pragma unroll
        for (int gg = 0; gg < 4; gg++) {
            float2 bb = *(const float2*)&Bg[gg][i * 64 + k0];
            float2 uu = *(const float2*)&Ug[gg][i * 64 + k0];
            bias2[gg] = packab(bb.x, bb.y);
            u2[gg]    = packab(uu.x, uu.y);
        }
    }
    const float fa0 = Fa[k0 * 32 + i];
    const float fa1 = Fa[(k0 + 1) * 32 + i];
    const float FabV = Fab[i];

    // ---- state ----
    unsigned long long acc[4][2];                 // [gate][b]
    float c[2][2], gacc[2][2], hn[2][2], den[2];  // [kappa][b]
#pragma unroll
    for (int b = 0; b < 2; b++) {
        c[0][b] = c[1][b] = 0.0f;
        gacc[0][b] = gacc[1][b] = 0.0f;
        hn[0][b] = hn[1][b] = 0.0f;
        den[b] = 0.0f;
    }

    const ulonglong2* W2 = (const ulonglong2*)(sm + SMW);  // 16B units; ROW j = 64 ull2
    const ulonglong2* Wt = W2 + wq;                        // this thread's column base
    int cur = 0;

    for (int t = 0; t < 256; t++) {
        // init acc = bias + x*U
        const float2 xv = *(const float2*)&sm[SMX + t * 32 + bq * 2];
        unsigned long long xv2[2];
        xv2[0] = pack2(xv.x);
        xv2[1] = pack2(xv.y);
#pragma unroll
        for (int gg = 0; gg < 4; gg++)
#pragma unroll
            for (int b = 0; b < 2; b++) {
                acc[gg][b] = bias2[gg];
                fma2(acc[gg][b], u2[gg], xv2[b]);
            }

        // recurrent matvec: register-tiled outer product over j,
        // explicit depth-2 software pipeline (prefetch j+2 while computing j)
        const float* hbase = sm + SMH + cur * 2048 + bq * 2;
        float2 h_p[2];
        ulonglong2 wA_p[2], wB_p[2];
#pragma unroll
        for (int jj = 0; jj < 2; jj++) {
            h_p[jj]  = *(const float2*)&hbase[jj * 32];
            wA_p[jj] = Wt[jj * 64];
            wB_p[jj] = Wt[jj * 64 + 1];
        }
#pragma unroll 8
        for (int j = 0; j < 64; j++) {
            const int s = j & 1;
            const float2 hf = h_p[s];
            const ulonglong2 wA = wA_p[s];
            const ulonglong2 wB = wB_p[s];
            if (j < 62) {
                h_p[s]  = *(const float2*)&hbase[(j + 2) * 32];
                wA_p[s] = Wt[(j + 2) * 64];
                wB_p[s] = Wt[(j + 2) * 64 + 1];
            }
            const unsigned long long h2a = pack2(hf.x);
            const unsigned long long h2b = pack2(hf.y);
            fma2(acc[0][0], wA.x, h2a); fma2(acc[0][1], wA.x, h2b);
            fma2(acc[1][0], wA.y, h2a); fma2(acc[1][1], wA.y, h2b);
            fma2(acc[2][0], wB.x, h2a); fma2(acc[2][1], wB.x, h2b);
            fma2(acc[3][0], wB.y, h2a); fma2(acc[3][1], wB.y, h2b);
        }

        // gate nonlinearities + state update + alpha partial
        float sp[2];
#pragma unroll
        for (int b = 0; b < 2; b++) {
            float2 jv = unpack2(acc[0][b]);
            float2 iv = unpack2(acc[1][b]);
            float2 fv = unpack2(acc[2][b]);
            float2 ov = unpack2(acc[3][b]);
            {
                float jj = ftanh_(jv.x), ii = fsig(iv.x), ff = fsig(fv.x), oo = fsig(ov.x);
                float cn = fmaf(c[0][b], ff, ii * jj);
                c[0][b] = cn;
                hn[0][b] = oo * ftanh_(cn);
            }
            {
                float jj = ftanh_(jv.y), ii = fsig(iv.y), ff = fsig(fv.y), oo = fsig(ov.y);
                float cn = fmaf(c[1][b], ff, ii * jj);
                c[1][b] = cn;
                hn[1][b] = oo * ftanh_(cn);
            }
            sp[b] = fmaf(hn[0][b], fa0, hn[1][b] * fa1);
        }
        // reduce alpha partials over the 2 p-lanes sharing this b-pair
        sp[0] += __shfl_xor_sync(0xffffffffu, sp[0], 1);
        sp[1] += __shfl_xor_sync(0xffffffffu, sp[1], 1);
        if (p == 0)
            *(float2*)&sm[SMS + (t & 1) * 512 + w * 32 + bq * 2] =
                make_float2(sp[0], sp[1]);

        // write h_next (ping-pong buffer)
        float* hnext = sm + SMH + (cur ^ 1) * 2048;
        *(float2*)&hnext[k0 * 32 + bq * 2]       = make_float2(hn[0][0], hn[0][1]);
        *(float2*)&hnext[(k0 + 1) * 32 + bq * 2] = make_float2(hn[1][0], hn[1][1]);

        __syncthreads();  // single barrier per step

        // alpha score -> av; accumulate denominator and g_n
        // (4 interleaved accumulators to break the serial FADD chain)
        const float* spb = sm + SMS + (t & 1) * 512 + bq * 2;
        float s0a = FabV, s0b = 0.0f, s1a = FabV, s1b = 0.0f;
#pragma unroll
        for (int ww = 0; ww < 16; ww += 2) {
            float2 v0 = *(const float2*)&spb[ww * 32];
            float2 v1 = *(const float2*)&spb[(ww + 1) * 32];
            s0a += v0.x; s1a += v0.y;
            s0b += v1.x; s1b += v1.y;
        }
        float av[2];
        av[0] = __expf(ftanh_(s0a + s0b));
        av[1] = __expf(ftanh_(s1a + s1b));
#pragma unroll
        for (int b = 0; b < 2; b++) {
            den[b] += av[b];
            gacc[0][b] = fmaf(av[b], hn[0][b], gacc[0][b]);
            gacc[1][b] = fmaf(av[b], hn[1][b], gacc[1][b]);
        }
        if (w == 0 && p == 0)
            *(float2*)&g_aBuf[(i * 256 + t) * 128 + b0 + bq * 2] =
                make_float2(av[0], av[1]);

        cur ^= 1;
    }

    // ---- epilogue ----
#pragma unroll
    for (int b = 0; b < 2; b++) {
        int bg = b0 + bq * 2 + b;
        float invd = __fdividef(1.0f, den[b]);
        g_gBuf[(bg * 32 + i) * 64 + k0]      = gacc[0][b] * invd;
        g_gBuf[(bg * 32 + i) * 64 + k0 + 1]  = gacc[1][b] * invd;
        g_hTBuf[(bg * 32 + i) * 64 + k0]     = hn[0][b];
        g_hTBuf[(bg * 32 + i) * 64 + k0 + 1] = hn[1][b];
    }
    if (w == 0 && p == 0)
        *(float2*)&g_denBuf[i * 128 + b0 + bq * 2] = make_float2(den[0], den[1]);
}

// ===================== Kernel 2: normalize alphas into [B,T,D] =====================
__global__ void alpha_kernel(float* __restrict__ out) {
    int idx = blockIdx.x * 256 + threadIdx.x;  // 0 .. 1048575
    int b = idx >> 13;
    int r = idx & 8191;
    int t = r >> 5;
    int i = r & 31;
    float a = g_aBuf[(i * 256 + t) * 128 + b];
    float d = g_denBuf[i * 128 + b];
    out[128 + idx] = __fdividef(a, d);
}

// ===================== Kernel 3: output head =====================
__global__ void head_kernel(float* __restrict__ out,
                            const float* __restrict__ Phi_w, const float* __restrict__ Phi_b,
                            const float* __restrict__ Fbw, const float* __restrict__ Fbb) {
    int b = blockIdx.x;
    int i = threadIdx.x;
    const float* gp = g_gBuf + (b * 32 + i) * 64;
    const float* hp = g_hTBuf + (b * 32 + i) * 64;
    float mu = Phi_b[0];
    float bs = Fbb[0];
#pragma unroll 8
    for (int k = 0; k < 64; k++) {
        float gv = gp[k], hv = hp[k];
        mu = fmaf(gv, Phi_w[k], mu);
        mu = fmaf(hv, Phi_w[64 + k], mu);
        bs = fmaf(gv, Fbw[k], bs);
        bs = fmaf(hv, Fbw[64 + k], bs);
    }
    float e = __expf(ftanh_(bs));
    float se = e, sem = e * mu;
#pragma unroll
    for (int off = 16; off; off >>= 1) {
        se  += __shfl_xor_sync(0xffffffffu, se, off);
        sem += __shfl_xor_sync(0xffffffffu, sem, off);
    }
    out[128 + 1048576 + b * 32 + i] = __fdividef(e, se);  // betas
    if (i == 0) out[b] = __fdividef(sem, se);             // mean
}

// ===================== launch =====================
extern "C" void kernel_launch(void* const* d_in, const int* in_sizes, int n_in,
                              void* d_out, int out_size) {
    const float* x   = (const float*)d_in[0];
    const float* Uj  = (const float*)d_in[1];
    const float* Ui_ = (const float*)d_in[2];
    const float* Uf  = (const float*)d_in[3];
    const float* Uo  = (const float*)d_in[4];
    const float* Wj  = (const float*)d_in[5];
    const float* Wi_ = (const float*)d_in[6];
    const float* Wf  = (const float*)d_in[7];
    const float* Wo  = (const float*)d_in[8];
    const float* bj  = (const float*)d_in[9];
    const float* bi_ = (const float*)d_in[10];
    const float* bf  = (const float*)d_in[11];
    const float* bo  = (const float*)d_in[12];
    const float* Fa  = (const float*)d_in[13];
    const float* Fab = (const float*)d_in[14];
    const float* Fbw = (const float*)d_in[15];
    const float* Fbb = (const float*)d_in[16];
    const float* Pw  = (const float*)d_in[17];
    const float* Pb  = (const float*)d_in[18];
    float* out = (float*)d_out;

    size_t smem = SMTOT * sizeof(float);  // ~116 KB
    cudaFuncSetAttribute(lstm_kernel, cudaFuncAttributeMaxDynamicSharedMemorySize, (int)smem);

    lstm_kernel<<<dim3(32, 4), 512, smem>>>(x, Uj, Ui_, Uf, Uo, Wj, Wi_, Wf, Wo,
                                            bj, bi_, bf, bo, Fa, Fab);
    alpha_kernel<<<4096, 256>>>(out);
    head_kernel<<<128, 32>>>(out, Pw, Pb, Fbw, Fbb);
}

// round 6
// speedup vs baseline: 1.0160x; 1.0160x over previous
#include <cuda_runtime.h>

// Problem constants
#define B_DIM 128
#define T_DIM 256
#define D_DIM 32
#define N_DIM 64

// Scratch (device globals: no allocation allowed)
__device__ float g_aBuf[D_DIM * T_DIM * B_DIM];   // [i][t][b] unnormalized alphas
__device__ float g_denBuf[D_DIM * B_DIM];         // [i][b]
__device__ float g_gBuf[B_DIM * D_DIM * N_DIM];   // [b][i][k] g_n (normalized)
__device__ float g_hTBuf[B_DIM * D_DIM * N_DIM];  // [b][i][k] h_T

// ---------------- math helpers ----------------
static __device__ __forceinline__ float tanha(float x) {
    float y;
    asm("tanh.approx.f32 %0, %1;" : "=f"(y) : "f"(x));
    return y;
}
static __device__ __forceinline__ float siga(float x) {
    return fmaf(tanha(0.5f * x), 0.5f, 0.5f);
}
// packed f32x2 fma (Blackwell)
static __device__ __forceinline__ void fma2(unsigned long long& a,
                                            unsigned long long b,
                                            unsigned long long c) {
    asm("fma.rn.f32x2 %0, %1, %2, %0;" : "+l"(a) : "l"(b), "l"(c));
}
static __device__ __forceinline__ unsigned long long pack2(float x) {
    unsigned long long r;
    asm("mov.b64 %0, {%1, %1};" : "=l"(r) : "f"(x));
    return r;
}
static __device__ __forceinline__ unsigned long long packab(float x, float y) {
    unsigned long long r;
    asm("mov.b64 %0, {%1, %2};" : "=l"(r) : "f"(x), "f"(y));
    return r;
}
static __device__ __forceinline__ float2 unpack2(unsigned long long a) {
    float lo, hi;
    asm("mov.b64 {%0, %1}, %2;" : "=f"(lo), "=f"(hi) : "l"(a));
    return make_float2(lo, hi);
}

// ---------------- shared memory layout (float offsets) ----------------
// W' interleaved: [j][kpair(32)][gate(4)][kappa(2)] -> row j = 256 floats = 64 ull2
// H  duplicated:  [j][b(32) x dup(2)]              -> row j = 64 floats
#define SMW 0          // 64 j * 256 = 16384 floats
#define SMX 16384      // x: 256 t * 32 b = 8192
#define SMH 24576      // h ping-pong (dup): 2 * (64 j * 64) = 8192
#define SMS 32768      // sp ping-pong: 2 * (16 w * 32 b) = 1024
#define SMTOT 33792    // floats -> 135168 bytes

// ===================== Kernel 1: fused LSTM + streamed attention =====================
// grid = (32 i, 4 b-chunks), block = 512 = 16 warps (4 per SMSP).
// warp w owns k in [4w, 4w+4); lane = bq*2 + p: p -> k-pair (k0 = 4w+2p), bq -> b-pair.
__global__ void __launch_bounds__(512, 1)
lstm_kernel(const float* __restrict__ x,
            const float* __restrict__ Uj, const float* __restrict__ Ui_,
            const float* __restrict__ Uf, const float* __restrict__ Uo,
            const float* __restrict__ Wj, const float* __restrict__ Wi_,
            const float* __restrict__ Wf, const float* __restrict__ Wo,
            const float* __restrict__ bj, const float* __restrict__ bi_,
            const float* __restrict__ bf, const float* __restrict__ bo,
            const float* __restrict__ Fa, const float* __restrict__ Fab) {
    extern __shared__ float sm[];
    const int tid  = threadIdx.x;
    const int w    = tid >> 5;
    const int lane = tid & 31;
    const int p    = lane & 1;
    const int bq   = lane >> 1;
    const int i    = blockIdx.x;
    const int b0   = blockIdx.y << 5;
    const int k0   = w * 4 + p * 2;        // first k of this thread's pair
    const int wq   = w * 4 + p * 2;        // ull2 base offset within W row j

    // ---- cooperative loads ----
    {
        const float* Wg[4] = {Wj, Wi_, Wf, Wo};
#pragma unroll
        for (int gg = 0; gg < 4; gg++) {
            const float* src = Wg[gg];
            for (int idx = tid; idx < 4096; idx += 512) {
                int j = idx >> 6, k = idx & 63;
                sm[SMW + j * 256 + (k >> 1) * 8 + gg * 2 + (k & 1)] =
                    src[(j * 32 + i) * 64 + k];
            }
        }
        for (int idx = tid; idx < 8192; idx += 512) {
            int t = idx >> 5, bl = idx & 31;
            sm[SMX + idx] = x[((b0 + bl) * 256 + t) * 32 + i];
        }
        for (int idx = tid; idx < 8192; idx += 512) sm[SMH + idx] = 0.0f;
    }
    __syncthreads();

    // ---- per-thread constants (registers) ----
    unsigned long long bias2[4], u2[4];
    {
        const float* Bg[4] = {bj, bi_, bf, bo};
        const float* Ug[4] = {Uj, Ui_, Uf, Uo};
#pragma unroll
        for (int gg = 0; gg < 4; gg++) {
            float2 bb = *(const float2*)&Bg[gg][i * 64 + k0];
            float2 uu = *(const float2*)&Ug[gg][i * 64 + k0];
            bias2[gg] = packab(bb.x, bb.y);
            u2[gg]    = packab(uu.x, uu.y);
        }
    }
    const float fa0 = Fa[k0 * 32 + i];
    const float fa1 = Fa[(k0 + 1) * 32 + i];
    const float FabV = Fab[i];

    // ---- state ----
    unsigned long long acc[4][2];                 // [gate][b]
    float c[2][2], gacc[2][2], hn[2][2], den[2];  // [kappa][b]
#pragma unroll
    for (int b = 0; b < 2; b++) {
        c[0][b] = c[1][b] = 0.0f;
        gacc[0][b] = gacc[1][b] = 0.0f;
        hn[0][b] = hn[1][b] = 0.0f;
        den[b] = 0.0f;
    }

    const ulonglong2* W2 = (const ulonglong2*)(sm + SMW);  // ROW j = 64 ull2
    const ulonglong2* Wt = W2 + wq;                        // this thread's column base
    int cur = 0;

    for (int t = 0; t < 256; t++) {
        // init acc = bias + x*U
        const float2 xv = *(const float2*)&sm[SMX + t * 32 + bq * 2];
        unsigned long long xv2[2];
        xv2[0] = pack2(xv.x);
        xv2[1] = pack2(xv.y);
#pragma unroll
        for (int gg = 0; gg < 4; gg++)
#pragma unroll
            for (int b = 0; b < 2; b++) {
                acc[gg][b] = bias2[gg];
                fma2(acc[gg][b], u2[gg], xv2[b]);
            }

        // recurrent matvec: register-tiled outer product over j.
        // h is stored DUPLICATED [j][b][2] -> one LDS.128 gives both packed
        // f32x2 operands {h[b0],h[b0]}, {h[b1],h[b1]} with zero movs.
        const ulonglong2* hdup =
            (const ulonglong2*)(sm + SMH + cur * 4096) + bq;  // row stride 16 ull2
#pragma unroll 4
        for (int j = 0; j < 64; j++) {
            const ulonglong2 hd = hdup[j * 16];
            const ulonglong2 wA = Wt[j * 64];      // gates 0,1 (kappa-packed)
            const ulonglong2 wB = Wt[j * 64 + 1];  // gates 2,3
            fma2(acc[0][0], wA.x, hd.x); fma2(acc[0][1], wA.x, hd.y);
            fma2(acc[1][0], wA.y, hd.x); fma2(acc[1][1], wA.y, hd.y);
            fma2(acc[2][0], wB.x, hd.x); fma2(acc[2][1], wB.x, hd.y);
            fma2(acc[3][0], wB.y, hd.x); fma2(acc[3][1], wB.y, hd.y);
        }

        // gate nonlinearities (HW tanh) + state update + alpha partial
        float sp[2];
#pragma unroll
        for (int b = 0; b < 2; b++) {
            float2 jv = unpack2(acc[0][b]);
            float2 iv = unpack2(acc[1][b]);
            float2 fv = unpack2(acc[2][b]);
            float2 ov = unpack2(acc[3][b]);
            {
                float jj = tanha(jv.x), ii = siga(iv.x), ff = siga(fv.x), oo = siga(ov.x);
                float cn = fmaf(c[0][b], ff, ii * jj);
                c[0][b] = cn;
                hn[0][b] = oo * tanha(cn);
            }
            {
                float jj = tanha(jv.y), ii = siga(iv.y), ff = siga(fv.y), oo = siga(ov.y);
                float cn = fmaf(c[1][b], ff, ii * jj);
                c[1][b] = cn;
                hn[1][b] = oo * tanha(cn);
            }
            sp[b] = fmaf(hn[0][b], fa0, hn[1][b] * fa1);
        }
        // reduce alpha partials over the 2 p-lanes sharing this b-pair
        sp[0] += __shfl_xor_sync(0xffffffffu, sp[0], 1);
        sp[1] += __shfl_xor_sync(0xffffffffu, sp[1], 1);
        if (p == 0)
            *(float2*)&sm[SMS + (t & 1) * 512 + w * 32 + bq * 2] =
                make_float2(sp[0], sp[1]);

        // write h_next (duplicated layout, ping-pong buffer)
        float* hnext = sm + SMH + (cur ^ 1) * 4096;
        *(float4*)&hnext[k0 * 64 + bq * 4] =
            make_float4(hn[0][0], hn[0][0], hn[0][1], hn[0][1]);
        *(float4*)&hnext[(k0 + 1) * 64 + bq * 4] =
            make_float4(hn[1][0], hn[1][0], hn[1][1], hn[1][1]);

        __syncthreads();  // single barrier per step

        // alpha score -> av; accumulate denominator and g_n
        const float* spb = sm + SMS + (t & 1) * 512 + bq * 2;
        float s0a = FabV, s0b = 0.0f, s1a = FabV, s1b = 0.0f;
#pragma unroll
        for (int ww = 0; ww < 16; ww += 2) {
            float2 v0 = *(const float2*)&spb[ww * 32];
            float2 v1 = *(const float2*)&spb[(ww + 1) * 32];
            s0a += v0.x; s1a += v0.y;
            s0b += v1.x; s1b += v1.y;
        }
        float av[2];
        av[0] = __expf(tanha(s0a + s0b));
        av[1] = __expf(tanha(s1a + s1b));
#pragma unroll
        for (int b = 0; b < 2; b++) {
            den[b] += av[b];
            gacc[0][b] = fmaf(av[b], hn[0][b], gacc[0][b]);
            gacc[1][b] = fmaf(av[b], hn[1][b], gacc[1][b]);
        }
        if (w == 0 && p == 0)
            *(float2*)&g_aBuf[(i * 256 + t) * 128 + b0 + bq * 2] =
                make_float2(av[0], av[1]);

        cur ^= 1;
    }

    // ---- epilogue ----
#pragma unroll
    for (int b = 0; b < 2; b++) {
        int bg = b0 + bq * 2 + b;
        float invd = __fdividef(1.0f, den[b]);
        g_gBuf[(bg * 32 + i) * 64 + k0]      = gacc[0][b] * invd;
        g_gBuf[(bg * 32 + i) * 64 + k0 + 1]  = gacc[1][b] * invd;
        g_hTBuf[(bg * 32 + i) * 64 + k0]     = hn[0][b];
        g_hTBuf[(bg * 32 + i) * 64 + k0 + 1] = hn[1][b];
    }
    if (w == 0 && p == 0)
        *(float2*)&g_denBuf[i * 128 + b0 + bq * 2] = make_float2(den[0], den[1]);
}

// ===================== Kernel 2: normalize alphas into [B,T,D] =====================
__global__ void alpha_kernel(float* __restrict__ out) {
    int idx = blockIdx.x * 256 + threadIdx.x;  // 0 .. 1048575
    int b = idx >> 13;
    int r = idx & 8191;
    int t = r >> 5;
    int i = r & 31;
    float a = g_aBuf[(i * 256 + t) * 128 + b];
    float d = g_denBuf[i * 128 + b];
    out[128 + idx] = __fdividef(a, d);
}

// ===================== Kernel 3: output head =====================
__global__ void head_kernel(float* __restrict__ out,
                            const float* __restrict__ Phi_w, const float* __restrict__ Phi_b,
                            const float* __restrict__ Fbw, const float* __restrict__ Fbb) {
    int b = blockIdx.x;
    int i = threadIdx.x;
    const float* gp = g_gBuf + (b * 32 + i) * 64;
    const float* hp = g_hTBuf + (b * 32 + i) * 64;
    float mu = Phi_b[0];
    float bs = Fbb[0];
#pragma unroll 8
    for (int k = 0; k < 64; k++) {
        float gv = gp[k], hv = hp[k];
        mu = fmaf(gv, Phi_w[k], mu);
        mu = fmaf(hv, Phi_w[64 + k], mu);
        bs = fmaf(gv, Fbw[k], bs);
        bs = fmaf(hv, Fbw[64 + k], bs);
    }
    float e = __expf(tanha(bs));
    float se = e, sem = e * mu;
#pragma unroll
    for (int off = 16; off; off >>= 1) {
        se  += __shfl_xor_sync(0xffffffffu, se, off);
        sem += __shfl_xor_sync(0xffffffffu, sem, off);
    }
    out[128 + 1048576 + b * 32 + i] = __fdividef(e, se);  // betas
    if (i == 0) out[b] = __fdividef(sem, se);             // mean
}

// ===================== launch =====================
extern "C" void kernel_launch(void* const* d_in, const int* in_sizes, int n_in,
                              void* d_out, int out_size) {
    const float* x   = (const float*)d_in[0];
    const float* Uj  = (const float*)d_in[1];
    const float* Ui_ = (const float*)d_in[2];
    const float* Uf  = (const float*)d_in[3];
    const float* Uo  = (const float*)d_in[4];
    const float* Wj  = (const float*)d_in[5];
    const float* Wi_ = (const float*)d_in[6];
    const float* Wf  = (const float*)d_in[7];
    const float* Wo  = (const float*)d_in[8];
    const float* bj  = (const float*)d_in[9];
    const float* bi_ = (const float*)d_in[10];
    const float* bf  = (const float*)d_in[11];
    const float* bo  = (const float*)d_in[12];
    const float* Fa  = (const float*)d_in[13];
    const float* Fab = (const float*)d_in[14];
    const float* Fbw = (const float*)d_in[15];
    const float* Fbb = (const float*)d_in[16];
    const float* Pw  = (const float*)d_in[17];
    const float* Pb  = (const float*)d_in[18];
    float* out = (float*)d_out;

    size_t smem = SMTOT * sizeof(float);  // ~132 KB
    cudaFuncSetAttribute(lstm_kernel, cudaFuncAttributeMaxDynamicSharedMemorySize, (int)smem);

    lstm_kernel<<<dim3(32, 4), 512, smem>>>(x, Uj, Ui_, Uf, Uo, Wj, Wi_, Wf, Wo,
                                            bj, bi_, bf, bo, Fa, Fab);
    alpha_kernel<<<4096, 256>>>(out);
    head_kernel<<<128, 32>>>(out, Pw, Pb, Fbw, Fbb);
}

// round 7
// speedup vs baseline: 1.5799x; 1.5550x over previous
#include <cuda_runtime.h>

// Problem constants
#define B_DIM 128
#define T_DIM 256
#define D_DIM 32
#define N_DIM 64

// Scratch (device globals: no allocation allowed)
__device__ float g_aBuf[D_DIM * T_DIM * B_DIM];   // [i][t][b] unnormalized alphas
__device__ float g_denBuf[D_DIM * B_DIM];         // [i][b]
__device__ float g_gBuf[B_DIM * D_DIM * N_DIM];   // [b][i][k] g_n (normalized)
__device__ float g_hTBuf[B_DIM * D_DIM * N_DIM];  // [b][i][k] h_T

// ---------------- math helpers ----------------
static __device__ __forceinline__ float tanha(float x) {
    float y;
    asm("tanh.approx.f32 %0, %1;" : "=f"(y) : "f"(x));
    return y;
}
static __device__ __forceinline__ float siga(float x) {
    return fmaf(tanha(0.5f * x), 0.5f, 0.5f);
}
static __device__ __forceinline__ unsigned cvt_tf32(float x) {
    unsigned r;
    asm("cvt.rna.tf32.f32 %0, %1;" : "=r"(r) : "f"(x));
    return r;
}
// m16n8k8 tf32 MMA, C += A*B  (A row-major frag, B col-major frag)
static __device__ __forceinline__ void mma8(float* C,
                                            unsigned a0, unsigned a1,
                                            unsigned a2, unsigned a3,
                                            unsigned b0, unsigned b1) {
    asm("mma.sync.aligned.m16n8k8.row.col.f32.tf32.tf32.f32 "
        "{%0,%1,%2,%3}, {%4,%5,%6,%7}, {%8,%9}, {%0,%1,%2,%3};"
        : "+f"(C[0]), "+f"(C[1]), "+f"(C[2]), "+f"(C[3])
        : "r"(a0), "r"(a1), "r"(a2), "r"(a3), "r"(b0), "r"(b1));
}

// ---------------- shared memory layout (float offsets) ----------------
// h buffers: 2 x [32 b][68 float2] interleaved {hi,lo}, padded (68 f2 = 136 f)
#define HB  0        // 2 * 4352 = 8704 floats
#define XS  8704     // x: 256 t * 32 b = 8192
#define SP  16896    // 16 w * 32 b = 512
#define AL  17408    // alpha double buffer: 2 * 32 = 64
#define INV 17472    // 32
#define SMTOT 17504  // floats -> 70016 bytes

// ===================== Kernel 1: fused LSTM via 3xTF32 mma.sync =====================
// grid = (32 i, 4 b-chunks), block = 512 = 16 warps.
// Per CTA step GEMM: C[32b x 256gk] = h[32b x 64j] * W'[64j x 256gk].
// Warp w owns 16 N-cols: n-tile0 = [k:(j,i)] for k=4w..4w+3, n-tile1 = [k:(f,o)].
// Lane (g = lane>>2, t4 = lane&3): C cells = 4 b-rows {g,g+8,g+16,g+24} x k=4w+t4 x 4 gates.
__global__ void __launch_bounds__(512, 1)
lstm_kernel(const float* __restrict__ x,
            const float* __restrict__ Uj, const float* __restrict__ Ui_,
            const float* __restrict__ Uf, const float* __restrict__ Uo,
            const float* __restrict__ Wj, const float* __restrict__ Wi_,
            const float* __restrict__ Wf, const float* __restrict__ Wo,
            const float* __restrict__ bj, const float* __restrict__ bi_,
            const float* __restrict__ bf, const float* __restrict__ bo,
            const float* __restrict__ Fa, const float* __restrict__ Fab) {
    extern __shared__ float sm[];
    const int tid  = threadIdx.x;
    const int w    = tid >> 5;
    const int lane = tid & 31;
    const int g    = lane >> 2;
    const int t4   = lane & 3;
    const int i    = blockIdx.x;
    const int b0   = blockIdx.y << 5;
    const int k    = 4 * w + t4;          // this lane's C-column k
    const int kB   = 4 * w + (g >> 1);    // this lane's B-fragment k-column

    // ---- cooperative smem init ----
    for (int idx = tid; idx < 8704; idx += 512) sm[HB + idx] = 0.0f;
    if (tid < 64) sm[AL + tid] = 0.0f;
    for (int idx = tid; idx < 8192; idx += 512) {
        int tt = idx >> 5, bl = idx & 31;
        sm[XS + idx] = x[((b0 + bl) * 256 + tt) * 32 + i];
    }

    // ---- stationary B (weight) fragments in registers, hi/lo tf32 split ----
    // B frag for k-tile kt, n-tile nt: b0: row j = kt*8+t4, col = g; b1: j+4.
    // col g -> k_out = 4w + (g>>1), gate = 2*nt + (g&1).
    unsigned Bhi[8][2][2], Blo[8][2][2];
#pragma unroll
    for (int kt = 0; kt < 8; kt++) {
#pragma unroll
        for (int nt = 0; nt < 2; nt++) {
            const float* Wp = (g & 1) ? (nt == 0 ? Wi_ : Wo)
                                      : (nt == 0 ? Wj : Wf);
#pragma unroll
            for (int r = 0; r < 2; r++) {
                int j = kt * 8 + t4 + 4 * r;
                float wv = Wp[(j * 32 + i) * 64 + kB];
                unsigned hi = cvt_tf32(wv);
                float lof = wv - __uint_as_float(hi);
                Bhi[kt][nt][r] = hi;
                Blo[kt][nt][r] = cvt_tf32(lof);
            }
        }
    }

    // ---- per-lane constants ----
    float Uv[4], Bv[4];
    Uv[0] = Uj[i * 64 + k];  Bv[0] = bj[i * 64 + k];
    Uv[1] = Ui_[i * 64 + k]; Bv[1] = bi_[i * 64 + k];
    Uv[2] = Uf[i * 64 + k];  Bv[2] = bf[i * 64 + k];
    Uv[3] = Uo[i * 64 + k];  Bv[3] = bo[i * 64 + k];
    const float fav  = Fa[k * 32 + i];
    const float FabV = Fab[i];

    // ---- state ----
    float cst[4], gacc[4], hn[4];
#pragma unroll
    for (int b = 0; b < 4; b++) { cst[b] = 0.0f; gacc[b] = 0.0f; hn[b] = 0.0f; }
    float den0 = 0.0f;  // used by warp 0 only (lane = b)

    __syncthreads();
    int cur = 0;

    for (int t = 0; t < 256; t++) {
        // ---- C init = bias + x*U ----
        float xv[4];
#pragma unroll
        for (int b = 0; b < 4; b++) xv[b] = sm[XS + t * 32 + g + 8 * b];
        float C[2][2][4];
#pragma unroll
        for (int mt = 0; mt < 2; mt++)
#pragma unroll
            for (int nt = 0; nt < 2; nt++)
#pragma unroll
                for (int r = 0; r < 4; r++) {
                    int gate = 2 * nt + (r & 1);
                    int bidx = 2 * mt + (r >> 1);
                    C[mt][nt][r] = fmaf(xv[bidx], Uv[gate], Bv[gate]);
                }

        // ---- MMA phase: C += h * W  (3xTF32) ----
        const float2* hb = (const float2*)(sm + HB + cur * 4352);
#pragma unroll
        for (int kt = 0; kt < 8; kt++) {
#pragma unroll
            for (int mt = 0; mt < 2; mt++) {
                int r0 = (g + 16 * mt) * 68 + kt * 8 + t4;
                int r1 = (g + 8 + 16 * mt) * 68 + kt * 8 + t4;
                float2 A0 = hb[r0], A1 = hb[r1], A2 = hb[r0 + 4], A3 = hb[r1 + 4];
                unsigned a0h = __float_as_uint(A0.x), a0l = __float_as_uint(A0.y);
                unsigned a1h = __float_as_uint(A1.x), a1l = __float_as_uint(A1.y);
                unsigned a2h = __float_as_uint(A2.x), a2l = __float_as_uint(A2.y);
                unsigned a3h = __float_as_uint(A3.x), a3l = __float_as_uint(A3.y);
                // lo*hi + hi*lo + hi*hi
                mma8(C[mt][0], a0l, a1l, a2l, a3l, Bhi[kt][0][0], Bhi[kt][0][1]);
                mma8(C[mt][1], a0l, a1l, a2l, a3l, Bhi[kt][1][0], Bhi[kt][1][1]);
                mma8(C[mt][0], a0h, a1h, a2h, a3h, Blo[kt][0][0], Blo[kt][0][1]);
                mma8(C[mt][1], a0h, a1h, a2h, a3h, Blo[kt][1][0], Blo[kt][1][1]);
                mma8(C[mt][0], a0h, a1h, a2h, a3h, Bhi[kt][0][0], Bhi[kt][0][1]);
                mma8(C[mt][1], a0h, a1h, a2h, a3h, Bhi[kt][1][0], Bhi[kt][1][1]);
            }
        }

        // ---- accumulate prev step's alpha into g_n (hn still holds h(t-1)) ----
        const int albPrev = AL + ((t & 1) ^ 1) * 32;
#pragma unroll
        for (int b = 0; b < 4; b++) {
            float avp = sm[albPrev + g + 8 * b];
            gacc[b] = fmaf(avp, hn[b], gacc[b]);
        }

        // ---- activations + state update + alpha partial ----
        float sp[4];
#pragma unroll
        for (int b = 0; b < 4; b++) {
            int mt = b >> 1, rb = (b & 1) << 1;
            float jj = tanha(C[mt][0][rb]);
            float ii = siga(C[mt][0][rb + 1]);
            float ff = siga(C[mt][1][rb]);
            float oo = siga(C[mt][1][rb + 1]);
            float cn = fmaf(cst[b], ff, ii * jj);
            cst[b] = cn;
            hn[b] = oo * tanha(cn);
            sp[b] = hn[b] * fav;
        }
        // reduce alpha partials over the 4 k-lanes (t4) of this g
#pragma unroll
        for (int b = 0; b < 4; b++) {
            sp[b] += __shfl_xor_sync(0xffffffffu, sp[b], 1);
            sp[b] += __shfl_xor_sync(0xffffffffu, sp[b], 2);
        }
        if (t4 == 0) {
#pragma unroll
            for (int b = 0; b < 4; b++) sm[SP + w * 32 + g + 8 * b] = sp[b];
        }

        // ---- write h(t) hi/lo to ping-pong buffer ----
        float2* hw = (float2*)(sm + HB + (cur ^ 1) * 4352);
#pragma unroll
        for (int b = 0; b < 4; b++) {
            unsigned hi = cvt_tf32(hn[b]);
            float lof = hn[b] - __uint_as_float(hi);
            unsigned lo = cvt_tf32(lof);
            hw[(g + 8 * b) * 68 + k] =
                make_float2(__uint_as_float(hi), __uint_as_float(lo));
        }

        __syncthreads();  // barrier A: sp(t), h(t) visible

        // ---- warp 0: alpha(t) = exp(tanh(score)) per b ----
        if (w == 0) {
            float s0 = FabV, s1 = 0.0f, s2 = 0.0f, s3 = 0.0f;
#pragma unroll
            for (int ww = 0; ww < 16; ww += 4) {
                s0 += sm[SP + ww * 32 + lane];
                s1 += sm[SP + (ww + 1) * 32 + lane];
                s2 += sm[SP + (ww + 2) * 32 + lane];
                s3 += sm[SP + (ww + 3) * 32 + lane];
            }
            float av = __expf(tanha((s0 + s1) + (s2 + s3)));
            den0 += av;
            sm[AL + (t & 1) * 32 + lane] = av;
            g_aBuf[(i * 256 + t) * 128 + b0 + lane] = av;
        }

        __syncthreads();  // barrier B: alpha(t) visible
        cur ^= 1;
    }

    // ---- drain: accumulate alpha(255) ----
#pragma unroll
    for (int b = 0; b < 4; b++) {
        float avp = sm[AL + 32 + g + 8 * b];  // (255&1)=1 buffer
        gacc[b] = fmaf(avp, hn[b], gacc[b]);
    }
    if (w == 0) {
        sm[INV + lane] = __fdividef(1.0f, den0);
        g_denBuf[i * 128 + b0 + lane] = den0;
    }
    __syncthreads();

    // ---- epilogue: write g_n and h_T ----
#pragma unroll
    for (int b = 0; b < 4; b++) {
        int bg = b0 + g + 8 * b;
        float invd = sm[INV + g + 8 * b];
        g_gBuf[(bg * 32 + i) * 64 + k]  = gacc[b] * invd;
        g_hTBuf[(bg * 32 + i) * 64 + k] = hn[b];
    }
}

// ===================== Kernel 2: normalize alphas into [B,T,D] =====================
__global__ void alpha_kernel(float* __restrict__ out) {
    int idx = blockIdx.x * 256 + threadIdx.x;  // 0 .. 1048575
    int b = idx >> 13;
    int r = idx & 8191;
    int t = r >> 5;
    int i = r & 31;
    float a = g_aBuf[(i * 256 + t) * 128 + b];
    float d = g_denBuf[i * 128 + b];
    out[128 + idx] = __fdividef(a, d);
}

// ===================== Kernel 3: output head =====================
__global__ void head_kernel(float* __restrict__ out,
                            const float* __restrict__ Phi_w, const float* __restrict__ Phi_b,
                            const float* __restrict__ Fbw, const float* __restrict__ Fbb) {
    int b = blockIdx.x;
    int i = threadIdx.x;
    const float* gp = g_gBuf + (b * 32 + i) * 64;
    const float* hp = g_hTBuf + (b * 32 + i) * 64;
    float mu = Phi_b[0];
    float bs = Fbb[0];
#pragma unroll 8
    for (int kk = 0; kk < 64; kk++) {
        float gv = gp[kk], hv = hp[kk];
        mu = fmaf(gv, Phi_w[kk], mu);
        mu = fmaf(hv, Phi_w[64 + kk], mu);
        bs = fmaf(gv, Fbw[kk], bs);
        bs = fmaf(hv, Fbw[64 + kk], bs);
    }
    float e = __expf(tanha(bs));
    float se = e, sem = e * mu;
#pragma unroll
    for (int off = 16; off; off >>= 1) {
        se  += __shfl_xor_sync(0xffffffffu, se, off);
        sem += __shfl_xor_sync(0xffffffffu, sem, off);
    }
    out[128 + 1048576 + b * 32 + i] = __fdividef(e, se);  // betas
    if (i == 0) out[b] = __fdividef(sem, se);             // mean
}

// ===================== launch =====================
extern "C" void kernel_launch(void* const* d_in, const int* in_sizes, int n_in,
                              void* d_out, int out_size) {
    const float* x   = (const float*)d_in[0];
    const float* Uj  = (const float*)d_in[1];
    const float* Ui_ = (const float*)d_in[2];
    const float* Uf  = (const float*)d_in[3];
    const float* Uo  = (const float*)d_in[4];
    const float* Wj  = (const float*)d_in[5];
    const float* Wi_ = (const float*)d_in[6];
    const float* Wf  = (const float*)d_in[7];
    const float* Wo  = (const float*)d_in[8];
    const float* bj  = (const float*)d_in[9];
    const float* bi_ = (const float*)d_in[10];
    const float* bf  = (const float*)d_in[11];
    const float* bo  = (const float*)d_in[12];
    const float* Fa  = (const float*)d_in[13];
    const float* Fab = (const float*)d_in[14];
    const float* Fbw = (const float*)d_in[15];
    const float* Fbb = (const float*)d_in[16];
    const float* Pw  = (const float*)d_in[17];
    const float* Pb  = (const float*)d_in[18];
    float* out = (float*)d_out;

    size_t smem = SMTOT * sizeof(float);  // ~68 KB
    cudaFuncSetAttribute(lstm_kernel, cudaFuncAttributeMaxDynamicSharedMemorySize, (int)smem);

    lstm_kernel<<<dim3(32, 4), 512, smem>>>(x, Uj, Ui_, Uf, Uo, Wj, Wi_, Wf, Wo,
                                            bj, bi_, bf, bo, Fa, Fab);
    alpha_kernel<<<4096, 256>>>(out);
    head_kernel<<<128, 32>>>(out, Pw, Pb, Fbw, Fbb);
}

// round 8
// speedup vs baseline: 1.8867x; 1.1942x over previous
#include <cuda_runtime.h>

// Problem constants
#define B_DIM 128
#define T_DIM 256
#define D_DIM 32
#define N_DIM 64

// Scratch (device globals: no allocation allowed)
__device__ float g_aBuf[D_DIM * T_DIM * B_DIM];   // [i][t][b] unnormalized alphas
__device__ float g_denBuf[D_DIM * B_DIM];         // [i][b]
__device__ float g_gBuf[B_DIM * D_DIM * N_DIM];   // [b][i][k] g_n (normalized)
__device__ float g_hTBuf[B_DIM * D_DIM * N_DIM];  // [b][i][k] h_T

// ---------------- math helpers ----------------
static __device__ __forceinline__ float tanha(float x) {
    float y;
    asm("tanh.approx.f32 %0, %1;" : "=f"(y) : "f"(x));
    return y;
}
static __device__ __forceinline__ float siga(float x) {
    return fmaf(tanha(0.5f * x), 0.5f, 0.5f);
}
static __device__ __forceinline__ unsigned cvt_tf32(float x) {
    unsigned r;
    asm("cvt.rna.tf32.f32 %0, %1;" : "=r"(r) : "f"(x));
    return r;
}
// m16n8k8 tf32 MMA, C += A*B  (A row-major frag, B col-major frag)
static __device__ __forceinline__ void mma8(float* C,
                                            unsigned a0, unsigned a1,
                                            unsigned a2, unsigned a3,
                                            unsigned b0, unsigned b1) {
    asm("mma.sync.aligned.m16n8k8.row.col.f32.tf32.tf32.f32 "
        "{%0,%1,%2,%3}, {%4,%5,%6,%7}, {%8,%9}, {%0,%1,%2,%3};"
        : "+f"(C[0]), "+f"(C[1]), "+f"(C[2]), "+f"(C[3])
        : "r"(a0), "r"(a1), "r"(a2), "r"(a3), "r"(b0), "r"(b1));
}
#define GBAR(gid) asm volatile("bar.sync %0, 256;" :: "r"((gid) + 1) : "memory")

// ---------------- shared memory layout (float offsets) ----------------
// x: [t][32 b].  h per group: 2 buffers x [16 rows][68 float2 {hi,lo}] (136 f/row).
#define XS  0        // 8192
#define HBF 8192     // 2 groups * 2 * 2176 = 8704
#define SPF 16896    // 2 groups * 8 w * 16 b = 256
#define ALF 17152    // 2 groups * 2 * 16 = 64
#define INVF 17216   // 2 * 16 = 32
#define SMTOT 17248  // floats -> 68992 bytes

// ===================== Kernel 1: fused LSTM via 2xTF32 mma.sync, 2 groups/CTA =====================
// grid = (32 i, 4 b-chunks), block = 512 = 2 groups x 8 warps.
// Group gid handles b rows [16*gid, 16*gid+16) of this chunk (M=16).
// Per group step GEMM: C[16b x 256gk] = h[16b x 64j] * tf32(W')[64j x 256gk], A split hi/lo.
// Warp wg owns k in [8wg, 8wg+8): 4 n-tiles: nt0=k(0..3)x(j,i), nt1=k(0..3)x(f,o),
//                                           nt2=k(4..7)x(j,i), nt3=k(4..7)x(f,o).
// Lane (g=lane>>2, t4=lane&3): C cells = b rows {g, g+8} x k {8wg+t4, 8wg+4+t4} x 4 gates.
__global__ void __launch_bounds__(512, 1)
lstm_kernel(const float* __restrict__ x,
            const float* __restrict__ Uj, const float* __restrict__ Ui_,
            const float* __restrict__ Uf, const float* __restrict__ Uo,
            const float* __restrict__ Wj, const float* __restrict__ Wi_,
            const float* __restrict__ Wf, const float* __restrict__ Wo,
            const float* __restrict__ bj, const float* __restrict__ bi_,
            const float* __restrict__ bf, const float* __restrict__ bo,
            const float* __restrict__ Fa, const float* __restrict__ Fab) {
    extern __shared__ float sm[];
    const int tid  = threadIdx.x;
    const int gid  = tid >> 8;            // group 0/1
    const int wg   = (tid >> 5) & 7;      // warp in group
    const int lane = tid & 31;
    const int g    = lane >> 2;
    const int t4   = lane & 3;
    const int i    = blockIdx.x;
    const int b0g  = (blockIdx.y << 5) + (gid << 4);  // global b base of this group

    // ---- cooperative smem init (full CTA) ----
    for (int idx = tid; idx < 8704; idx += 512) sm[HBF + idx] = 0.0f;
    if (tid < 64) sm[ALF + tid] = 0.0f;
    {
        const int cb0 = blockIdx.y << 5;
        for (int idx = tid; idx < 8192; idx += 512) {
            int tt = idx >> 5, bl = idx & 31;
            sm[XS + idx] = x[((cb0 + bl) * 256 + tt) * 32 + i];
        }
    }

    // ---- stationary B (weight) fragments, tf32 hi only ----
    // frag[kt][nt]: b0: row j = kt*8+t4, col g; b1: j+4.
    // col g -> k = 8wg + 4*(nt>>1) + (g>>1), gate = 2*(nt&1) + (g&1).
    unsigned Bhi[8][4][2];
    {
        const float* WgP[4] = {Wj, Wi_, Wf, Wo};
#pragma unroll
        for (int kt = 0; kt < 8; kt++)
#pragma unroll
            for (int nt = 0; nt < 4; nt++) {
                int kB = 8 * wg + ((nt >> 1) << 2) + (g >> 1);
                const float* Wp = WgP[((nt & 1) << 1) + (g & 1)];
#pragma unroll
                for (int r = 0; r < 2; r++) {
                    int j = kt * 8 + t4 + 4 * r;
                    Bhi[kt][nt][r] = cvt_tf32(Wp[(j * 32 + i) * 64 + kB]);
                }
            }
    }

    // ---- per-lane constants: 2 k-values x 4 gates ----
    float Uv[2][4], Bv[2][4], fav[2];
    {
        const float* Ug[4] = {Uj, Ui_, Uf, Uo};
        const float* Bg[4] = {bj, bi_, bf, bo};
#pragma unroll
        for (int ka = 0; ka < 2; ka++) {
            int kk = 8 * wg + 4 * ka + t4;
#pragma unroll
            for (int gg = 0; gg < 4; gg++) {
                Uv[ka][gg] = Ug[gg][i * 64 + kk];
                Bv[ka][gg] = Bg[gg][i * 64 + kk];
            }
            fav[ka] = Fa[kk * 32 + i];
        }
    }
    const float FabV = Fab[i];

    // ---- state: [ka][bhalf] ----
    float cst[2][2], gacc[2][2], hn[2][2];
#pragma unroll
    for (int ka = 0; ka < 2; ka++)
#pragma unroll
        for (int bh = 0; bh < 2; bh++) {
            cst[ka][bh] = 0.0f; gacc[ka][bh] = 0.0f; hn[ka][bh] = 0.0f;
        }
    float den0 = 0.0f;  // warp wg==0, lane<16 only

    __syncthreads();  // one full-CTA barrier before groups diverge
    int cur = 0;
    const int hbase = HBF + gid * 4352;
    const int spb   = SPF + gid * 128;
    const int albase = ALF + gid * 32;
    const int xb0   = (gid << 4) + g;  // x row index for bhalf 0

    for (int t = 0; t < 256; t++) {
        // ---- C init = bias + x*U ----
        const float xv0 = sm[XS + t * 32 + xb0];
        const float xv1 = sm[XS + t * 32 + xb0 + 8];
        float C[4][4];
#pragma unroll
        for (int nt = 0; nt < 4; nt++)
#pragma unroll
            for (int r = 0; r < 4; r++) {
                int gate = ((nt & 1) << 1) + (r & 1);
                int ka = nt >> 1;
                C[nt][r] = fmaf((r >> 1) ? xv1 : xv0, Uv[ka][gate], Bv[ka][gate]);
            }

        // ---- MMA: C += (A_hi + A_lo) * B_hi ----
        const float2* hb = (const float2*)(sm + hbase + cur * 2176);
#pragma unroll
        for (int kt = 0; kt < 8; kt++) {
            int c0 = kt * 8 + t4;
            float2 A0 = hb[g * 68 + c0];
            float2 A1 = hb[(g + 8) * 68 + c0];
            float2 A2 = hb[g * 68 + c0 + 4];
            float2 A3 = hb[(g + 8) * 68 + c0 + 4];
            unsigned a0h = __float_as_uint(A0.x), a0l = __float_as_uint(A0.y);
            unsigned a1h = __float_as_uint(A1.x), a1l = __float_as_uint(A1.y);
            unsigned a2h = __float_as_uint(A2.x), a2l = __float_as_uint(A2.y);
            unsigned a3h = __float_as_uint(A3.x), a3l = __float_as_uint(A3.y);
#pragma unroll
            for (int nt = 0; nt < 4; nt++) {
                mma8(C[nt], a0l, a1l, a2l, a3l, Bhi[kt][nt][0], Bhi[kt][nt][1]);
                mma8(C[nt], a0h, a1h, a2h, a3h, Bhi[kt][nt][0], Bhi[kt][nt][1]);
            }
        }

        // ---- accumulate prev step's alpha into g_n (hn holds h(t-1)) ----
        {
            const int alp = albase + (((t & 1) ^ 1) << 4);
            float av0 = sm[alp + g], av1 = sm[alp + g + 8];
#pragma unroll
            for (int ka = 0; ka < 2; ka++) {
                gacc[ka][0] = fmaf(av0, hn[ka][0], gacc[ka][0]);
                gacc[ka][1] = fmaf(av1, hn[ka][1], gacc[ka][1]);
            }
        }

        // ---- activations + state update + alpha partials ----
        float sp0 = 0.0f, sp1 = 0.0f;
#pragma unroll
        for (int ka = 0; ka < 2; ka++)
#pragma unroll
            for (int bh = 0; bh < 2; bh++) {
                int rb = bh << 1;
                float jj = tanha(C[2 * ka][rb]);
                float ii = siga(C[2 * ka][rb + 1]);
                float ff = siga(C[2 * ka + 1][rb]);
                float oo = siga(C[2 * ka + 1][rb + 1]);
                float cn = fmaf(cst[ka][bh], ff, ii * jj);
                cst[ka][bh] = cn;
                float hv = oo * tanha(cn);
                hn[ka][bh] = hv;
                if (bh == 0) sp0 = fmaf(hv, fav[ka], sp0);
                else         sp1 = fmaf(hv, fav[ka], sp1);
            }
        sp0 += __shfl_xor_sync(0xffffffffu, sp0, 1);
        sp0 += __shfl_xor_sync(0xffffffffu, sp0, 2);
        sp1 += __shfl_xor_sync(0xffffffffu, sp1, 1);
        sp1 += __shfl_xor_sync(0xffffffffu, sp1, 2);
        if (t4 == 0) {
            sm[spb + wg * 16 + g]     = sp0;
            sm[spb + wg * 16 + g + 8] = sp1;
        }

        // ---- write h(t) hi/lo to ping-pong buffer ----
        float2* hw = (float2*)(sm + hbase + (cur ^ 1) * 2176);
#pragma unroll
        for (int ka = 0; ka < 2; ka++) {
            int kk = 8 * wg + 4 * ka + t4;
#pragma unroll
            for (int bh = 0; bh < 2; bh++) {
                float hv = hn[ka][bh];
                unsigned hi = cvt_tf32(hv);
                float lof = hv - __uint_as_float(hi);
                hw[(g + 8 * bh) * 68 + kk] =
                    make_float2(__uint_as_float(hi), __uint_as_float(lof));
            }
        }

        GBAR(gid);  // barrier A: sp(t), h(t) visible within group

        // ---- warp 0 of group: alpha(t) per b ----
        if (wg == 0 && lane < 16) {
            float sA = FabV, sB = 0.0f;
#pragma unroll
            for (int ww = 0; ww < 8; ww += 2) {
                sA += sm[spb + ww * 16 + lane];
                sB += sm[spb + (ww + 1) * 16 + lane];
            }
            float av = __expf(tanha(sA + sB));
            den0 += av;
            sm[albase + ((t & 1) << 4) + lane] = av;
            g_aBuf[(i * 256 + t) * 128 + b0g + lane] = av;
        }

        GBAR(gid);  // barrier B: alpha(t) visible
        cur ^= 1;
    }

    // ---- drain: accumulate alpha(255) ((255&1)=1 buffer) ----
    {
        float av0 = sm[albase + 16 + g], av1 = sm[albase + 16 + g + 8];
#pragma unroll
        for (int ka = 0; ka < 2; ka++) {
            gacc[ka][0] = fmaf(av0, hn[ka][0], gacc[ka][0]);
            gacc[ka][1] = fmaf(av1, hn[ka][1], gacc[ka][1]);
        }
    }
    if (wg == 0 && lane < 16) {
        sm[INVF + gid * 16 + lane] = __fdividef(1.0f, den0);
        g_denBuf[i * 128 + b0g + lane] = den0;
    }
    GBAR(gid);

    // ---- epilogue: write g_n and h_T ----
    {
        float inv0 = sm[INVF + gid * 16 + g];
        float inv1 = sm[INVF + gid * 16 + g + 8];
#pragma unroll
        for (int ka = 0; ka < 2; ka++) {
            int kk = 8 * wg + 4 * ka + t4;
            int bg0 = b0g + g, bg1 = b0g + g + 8;
            g_gBuf[(bg0 * 32 + i) * 64 + kk]  = gacc[ka][0] * inv0;
            g_gBuf[(bg1 * 32 + i) * 64 + kk]  = gacc[ka][1] * inv1;
            g_hTBuf[(bg0 * 32 + i) * 64 + kk] = hn[ka][0];
            g_hTBuf[(bg1 * 32 + i) * 64 + kk] = hn[ka][1];
        }
    }
}

// ===================== Kernel 2: normalize alphas into [B,T,D] =====================
__global__ void alpha_kernel(float* __restrict__ out) {
    int idx = blockIdx.x * 256 + threadIdx.x;  // 0 .. 1048575
    int b = idx >> 13;
    int r = idx & 8191;
    int t = r >> 5;
    int i = r & 31;
    float a = g_aBuf[(i * 256 + t) * 128 + b];
    float d = g_denBuf[i * 128 + b];
    out[128 + idx] = __fdividef(a, d);
}

// ===================== Kernel 3: output head =====================
__global__ void head_kernel(float* __restrict__ out,
                            const float* __restrict__ Phi_w, const float* __restrict__ Phi_b,
                            const float* __restrict__ Fbw, const float* __restrict__ Fbb) {
    int b = blockIdx.x;
    int i = threadIdx.x;
    const float* gp = g_gBuf + (b * 32 + i) * 64;
    const float* hp = g_hTBuf + (b * 32 + i) * 64;
    float mu = Phi_b[0];
    float bs = Fbb[0];
#pragma unroll 8
    for (int kk = 0; kk < 64; kk++) {
        float gv = gp[kk], hv = hp[kk];
        mu = fmaf(gv, Phi_w[kk], mu);
        mu = fmaf(hv, Phi_w[64 + kk], mu);
        bs = fmaf(gv, Fbw[kk], bs);
        bs = fmaf(hv, Fbw[64 + kk], bs);
    }
    float e = __expf(tanha(bs));
    float se = e, sem = e * mu;
#pragma unroll
    for (int off = 16; off; off >>= 1) {
        se  += __shfl_xor_sync(0xffffffffu, se, off);
        sem += __shfl_xor_sync(0xffffffffu, sem, off);
    }
    out[128 + 1048576 + b * 32 + i] = __fdividef(e, se);  // betas
    if (i == 0) out[b] = __fdividef(sem, se);             // mean
}

// ===================== launch =====================
extern "C" void kernel_launch(void* const* d_in, const int* in_sizes, int n_in,
                              void* d_out, int out_size) {
    const float* x   = (const float*)d_in[0];
    const float* Uj  = (const float*)d_in[1];
    const float* Ui_ = (const float*)d_in[2];
    const float* Uf  = (const float*)d_in[3];
    const float* Uo  = (const float*)d_in[4];
    const float* Wj  = (const float*)d_in[5];
    const float* Wi_ = (const float*)d_in[6];
    const float* Wf  = (const float*)d_in[7];
    const float* Wo  = (const float*)d_in[8];
    const float* bj  = (const float*)d_in[9];
    const float* bi_ = (const float*)d_in[10];
    const float* bf  = (const float*)d_in[11];
    const float* bo  = (const float*)d_in[12];
    const float* Fa  = (const float*)d_in[13];
    const float* Fab = (const float*)d_in[14];
    const float* Fbw = (const float*)d_in[15];
    const float* Fbb = (const float*)d_in[16];
    const float* Pw  = (const float*)d_in[17];
    const float* Pb  = (const float*)d_in[18];
    float* out = (float*)d_out;

    size_t smem = SMTOT * sizeof(float);  // ~68 KB
    cudaFuncSetAttribute(lstm_kernel, cudaFuncAttributeMaxDynamicSharedMemorySize, (int)smem);

    lstm_kernel<<<dim3(32, 4), 512, smem>>>(x, Uj, Ui_, Uf, Uo, Wj, Wi_, Wf, Wo,
                                            bj, bi_, bf, bo, Fa, Fab);
    alpha_kernel<<<4096, 256>>>(out);
    head_kernel<<<128, 32>>>(out, Pw, Pb, Fbw, Fbb);
}

// round 9
// speedup vs baseline: 2.3183x; 1.2287x over previous
#include <cuda_runtime.h>

// Problem constants
#define B_DIM 128
#define T_DIM 256
#define D_DIM 32
#define N_DIM 64

// Scratch (device globals: no allocation allowed)
__device__ float g_aBuf[D_DIM * T_DIM * B_DIM];   // [i][t][b] unnormalized alphas
__device__ float g_denBuf[D_DIM * B_DIM];         // [i][b]
__device__ float g_gBuf[B_DIM * D_DIM * N_DIM];   // [b][i][k] g_n (normalized)
__device__ float g_hTBuf[B_DIM * D_DIM * N_DIM];  // [b][i][k] h_T

// ---------------- math helpers ----------------
static __device__ __forceinline__ float tanha(float x) {
    float y;
    asm("tanh.approx.f32 %0, %1;" : "=f"(y) : "f"(x));
    return y;
}
static __device__ __forceinline__ float siga(float x) {
    return fmaf(tanha(0.5f * x), 0.5f, 0.5f);
}
static __device__ __forceinline__ unsigned cvt_tf32(float x) {
    unsigned r;
    asm("cvt.rna.tf32.f32 %0, %1;" : "=r"(r) : "f"(x));
    return r;
}
// m16n8k8 tf32 MMA, C += A*B  (A row-major frag, B col-major frag)
static __device__ __forceinline__ void mma8(float* C,
                                            unsigned a0, unsigned a1,
                                            unsigned a2, unsigned a3,
                                            unsigned b0, unsigned b1) {
    asm("mma.sync.aligned.m16n8k8.row.col.f32.tf32.tf32.f32 "
        "{%0,%1,%2,%3}, {%4,%5,%6,%7}, {%8,%9}, {%0,%1,%2,%3};"
        : "+f"(C[0]), "+f"(C[1]), "+f"(C[2]), "+f"(C[3])
        : "r"(a0), "r"(a1), "r"(a2), "r"(a3), "r"(b0), "r"(b1));
}
#define GBAR(gid) asm volatile("bar.sync %0, 256;" :: "r"((gid) + 1) : "memory")

// ---------------- shared memory layout (float offsets) ----------------
// x: [t][32 b].  h per group: 2 buffers x [16 rows][68 float2 {hi,lo}].
// sp per group: 2 buffers (t&1) x [8 w][16 b].
#define XS   0       // 8192
#define HBF  8192    // 2 groups * 2 * 2176 = 8704
#define SPF  16896   // 2 groups * 2 * 128 = 512
#define INVF 17408   // 2 * 16 = 32
#define SMTOT 17440  // floats -> 69760 bytes

// ===================== Kernel 1: fused LSTM via 2xTF32 mma.sync, 2 groups/CTA =====================
// grid = (32 i, 4 b-chunks), block = 512 = 2 groups x 8 warps; ONE barrier per step.
// Group gid handles b rows [16*gid, 16*gid+16) (M=16).
// Warp wg owns k in [8wg, 8wg+8): nt0=k(0..3)x(j,i), nt1=k(0..3)x(f,o),
//                                 nt2=k(4..7)x(j,i), nt3=k(4..7)x(f,o).
// Lane (g=lane>>2, t4=lane&3): C cells = b rows {g, g+8} x k {8wg+t4, 8wg+4+t4} x 4 gates.
__global__ void __launch_bounds__(512, 1)
lstm_kernel(const float* __restrict__ x,
            const float* __restrict__ Uj, const float* __restrict__ Ui_,
            const float* __restrict__ Uf, const float* __restrict__ Uo,
            const float* __restrict__ Wj, const float* __restrict__ Wi_,
            const float* __restrict__ Wf, const float* __restrict__ Wo,
            const float* __restrict__ bj, const float* __restrict__ bi_,
            const float* __restrict__ bf, const float* __restrict__ bo,
            const float* __restrict__ Fa, const float* __restrict__ Fab) {
    extern __shared__ float sm[];
    const int tid  = threadIdx.x;
    const int gid  = tid >> 8;            // group 0/1
    const int wg   = (tid >> 5) & 7;      // warp in group
    const int lane = tid & 31;
    const int g    = lane >> 2;
    const int t4   = lane & 3;
    const int bl   = lane & 15;           // b-row for alpha compute
    const int i    = blockIdx.x;
    const int b0g  = (blockIdx.y << 5) + (gid << 4);

    // ---- cooperative smem init (full CTA) ----
    for (int idx = tid; idx < 8704; idx += 512) sm[HBF + idx] = 0.0f;
    {
        const int cb0 = blockIdx.y << 5;
        for (int idx = tid; idx < 8192; idx += 512) {
            int tt = idx >> 5, blx = idx & 31;
            sm[XS + idx] = x[((cb0 + blx) * 256 + tt) * 32 + i];
        }
    }

    // ---- stationary B (weight) fragments, tf32 hi only ----
    unsigned Bhi[8][4][2];
    {
        const float* WgP[4] = {Wj, Wi_, Wf, Wo};
#pragma unroll
        for (int kt = 0; kt < 8; kt++)
#pragma unroll
            for (int nt = 0; nt < 4; nt++) {
                int kB = 8 * wg + ((nt >> 1) << 2) + (g >> 1);
                const float* Wp = WgP[((nt & 1) << 1) + (g & 1)];
#pragma unroll
                for (int r = 0; r < 2; r++) {
                    int j = kt * 8 + t4 + 4 * r;
                    Bhi[kt][nt][r] = cvt_tf32(Wp[(j * 32 + i) * 64 + kB]);
                }
            }
    }

    // ---- per-lane constants: 2 k-values x 4 gates ----
    float Uv[2][4], Bv[2][4], fav[2];
    {
        const float* Ug[4] = {Uj, Ui_, Uf, Uo};
        const float* Bg[4] = {bj, bi_, bf, bo};
#pragma unroll
        for (int ka = 0; ka < 2; ka++) {
            int kk = 8 * wg + 4 * ka + t4;
#pragma unroll
            for (int gg = 0; gg < 4; gg++) {
                Uv[ka][gg] = Ug[gg][i * 64 + kk];
                Bv[ka][gg] = Bg[gg][i * 64 + kk];
            }
            fav[ka] = Fa[kk * 32 + i];
        }
    }
    const float FabV = Fab[i];

    // ---- state ----
    float cst[2][2], gacc[2][2], hn[2][2];
#pragma unroll
    for (int ka = 0; ka < 2; ka++)
#pragma unroll
        for (int bh = 0; bh < 2; bh++) {
            cst[ka][bh] = 0.0f; gacc[ka][bh] = 0.0f; hn[ka][bh] = 0.0f;
        }
    float den = 0.0f;  // per-lane, b = bl (redundant across warps)

    __syncthreads();
    int cur = 0;
    const int hbase  = HBF + gid * 4352;
    const int spbase = SPF + gid * 256;
    const int xb0    = (gid << 4) + g;

    for (int t = 0; t < 256; t++) {
        // ---- C init = bias + x*U ----
        const float xv0 = sm[XS + t * 32 + xb0];
        const float xv1 = sm[XS + t * 32 + xb0 + 8];
        float C[4][4];
#pragma unroll
        for (int nt = 0; nt < 4; nt++)
#pragma unroll
            for (int r = 0; r < 4; r++) {
                int gate = ((nt & 1) << 1) + (r & 1);
                int ka = nt >> 1;
                C[nt][r] = fmaf((r >> 1) ? xv1 : xv0, Uv[ka][gate], Bv[ka][gate]);
            }

        // ---- MMA: C += (A_hi + A_lo) * B_hi  (lo wave then hi wave per kt) ----
        const float2* hb = (const float2*)(sm + hbase + cur * 2176);
#pragma unroll
        for (int kt = 0; kt < 8; kt++) {
            int c0 = kt * 8 + t4;
            float2 A0 = hb[g * 68 + c0];
            float2 A1 = hb[(g + 8) * 68 + c0];
            float2 A2 = hb[g * 68 + c0 + 4];
            float2 A3 = hb[(g + 8) * 68 + c0 + 4];
            unsigned a0h = __float_as_uint(A0.x), a0l = __float_as_uint(A0.y);
            unsigned a1h = __float_as_uint(A1.x), a1l = __float_as_uint(A1.y);
            unsigned a2h = __float_as_uint(A2.x), a2l = __float_as_uint(A2.y);
            unsigned a3h = __float_as_uint(A3.x), a3l = __float_as_uint(A3.y);
#pragma unroll
            for (int nt = 0; nt < 4; nt++)
                mma8(C[nt], a0l, a1l, a2l, a3l, Bhi[kt][nt][0], Bhi[kt][nt][1]);
#pragma unroll
            for (int nt = 0; nt < 4; nt++)
                mma8(C[nt], a0h, a1h, a2h, a3h, Bhi[kt][nt][0], Bhi[kt][nt][1]);
        }

        // ---- activations + state update + alpha partials ----
        float sp0 = 0.0f, sp1 = 0.0f;
#pragma unroll
        for (int ka = 0; ka < 2; ka++)
#pragma unroll
            for (int bh = 0; bh < 2; bh++) {
                int rb = bh << 1;
                float jj = tanha(C[2 * ka][rb]);
                float ii = siga(C[2 * ka][rb + 1]);
                float ff = siga(C[2 * ka + 1][rb]);
                float oo = siga(C[2 * ka + 1][rb + 1]);
                float cn = fmaf(cst[ka][bh], ff, ii * jj);
                cst[ka][bh] = cn;
                float hv = oo * tanha(cn);
                hn[ka][bh] = hv;
                if (bh == 0) sp0 = fmaf(hv, fav[ka], sp0);
                else         sp1 = fmaf(hv, fav[ka], sp1);
            }
        sp0 += __shfl_xor_sync(0xffffffffu, sp0, 1);
        sp0 += __shfl_xor_sync(0xffffffffu, sp0, 2);
        sp1 += __shfl_xor_sync(0xffffffffu, sp1, 1);
        sp1 += __shfl_xor_sync(0xffffffffu, sp1, 2);
        const int spb = spbase + (t & 1) * 128;
        if (t4 == 0) {
            sm[spb + wg * 16 + g]     = sp0;
            sm[spb + wg * 16 + g + 8] = sp1;
        }

        // ---- write h(t) hi/lo to ping-pong buffer ----
        float2* hw = (float2*)(sm + hbase + (cur ^ 1) * 2176);
#pragma unroll
        for (int ka = 0; ka < 2; ka++) {
            int kk = 8 * wg + 4 * ka + t4;
#pragma unroll
            for (int bh = 0; bh < 2; bh++) {
                float hv = hn[ka][bh];
                unsigned hi = cvt_tf32(hv);
                float lof = hv - __uint_as_float(hi);
                hw[(g + 8 * bh) * 68 + kk] =
                    make_float2(__uint_as_float(hi), __uint_as_float(lof));
            }
        }

        GBAR(gid);  // ONE barrier per step: sp(t) + h(t) visible within group

        // ---- alpha(t): computed redundantly by every warp (fully parallel) ----
        {
            const float* spp = sm + spb;
            float sA = FabV, sB = 0.0f;
#pragma unroll
            for (int ww = 0; ww < 8; ww += 2) {
                sA += spp[ww * 16 + bl];
                sB += spp[(ww + 1) * 16 + bl];
            }
            float av = __expf(tanha(sA + sB));
            den += av;
            float av0 = __shfl_sync(0xffffffffu, av, g);
            float av1 = __shfl_sync(0xffffffffu, av, g + 8);
#pragma unroll
            for (int ka = 0; ka < 2; ka++) {
                gacc[ka][0] = fmaf(av0, hn[ka][0], gacc[ka][0]);
                gacc[ka][1] = fmaf(av1, hn[ka][1], gacc[ka][1]);
            }
            if (wg == 0 && lane < 16)
                g_aBuf[(i * 256 + t) * 128 + b0g + lane] = av;
        }

        cur ^= 1;
    }

    // ---- finalize denominators ----
    if (wg == 0 && lane < 16) {
        sm[INVF + gid * 16 + lane] = __fdividef(1.0f, den);
        g_denBuf[i * 128 + b0g + lane] = den;
    }
    GBAR(gid);

    // ---- epilogue: write g_n and h_T ----
    {
        float inv0 = sm[INVF + gid * 16 + g];
        float inv1 = sm[INVF + gid * 16 + g + 8];
#pragma unroll
        for (int ka = 0; ka < 2; ka++) {
            int kk = 8 * wg + 4 * ka + t4;
            int bg0 = b0g + g, bg1 = b0g + g + 8;
            g_gBuf[(bg0 * 32 + i) * 64 + kk]  = gacc[ka][0] * inv0;
            g_gBuf[(bg1 * 32 + i) * 64 + kk]  = gacc[ka][1] * inv1;
            g_hTBuf[(bg0 * 32 + i) * 64 + kk] = hn[ka][0];
            g_hTBuf[(bg1 * 32 + i) * 64 + kk] = hn[ka][1];
        }
    }
}

// ===================== Kernel 2: normalize alphas into [B,T,D] =====================
__global__ void alpha_kernel(float* __restrict__ out) {
    int idx = blockIdx.x * 256 + threadIdx.x;  // 0 .. 1048575
    int b = idx >> 13;
    int r = idx & 8191;
    int t = r >> 5;
    int i = r & 31;
    float a = g_aBuf[(i * 256 + t) * 128 + b];
    float d = g_denBuf[i * 128 + b];
    out[128 + idx] = __fdividef(a, d);
}

// ===================== Kernel 3: output head =====================
__global__ void head_kernel(float* __restrict__ out,
                            const float* __restrict__ Phi_w, const float* __restrict__ Phi_b,
                            const float* __restrict__ Fbw, const float* __restrict__ Fbb) {
    int b = blockIdx.x;
    int i = threadIdx.x;
    const float* gp = g_gBuf + (b * 32 + i) * 64;
    const float* hp = g_hTBuf + (b * 32 + i) * 64;
    float mu = Phi_b[0];
    float bs = Fbb[0];
#pragma unroll 8
    for (int kk = 0; kk < 64; kk++) {
        float gv = gp[kk], hv = hp[kk];
        mu = fmaf(gv, Phi_w[kk], mu);
        mu = fmaf(hv, Phi_w[64 + kk], mu);
        bs = fmaf(gv, Fbw[kk], bs);
        bs = fmaf(hv, Fbw[64 + kk], bs);
    }
    float e = __expf(tanha(bs));
    float se = e, sem = e * mu;
#pragma unroll
    for (int off = 16; off; off >>= 1) {
        se  += __shfl_xor_sync(0xffffffffu, se, off);
        sem += __shfl_xor_sync(0xffffffffu, sem, off);
    }
    out[128 + 1048576 + b * 32 + i] = __fdividef(e, se);  // betas
    if (i == 0) out[b] = __fdividef(sem, se);             // mean
}

// ===================== launch =====================
extern "C" void kernel_launch(void* const* d_in, const int* in_sizes, int n_in,
                              void* d_out, int out_size) {
    const float* x   = (const float*)d_in[0];
    const float* Uj  = (const float*)d_in[1];
    const float* Ui_ = (const float*)d_in[2];
    const float* Uf  = (const float*)d_in[3];
    const float* Uo  = (const float*)d_in[4];
    const float* Wj  = (const float*)d_in[5];
    const float* Wi_ = (const float*)d_in[6];
    const float* Wf  = (const float*)d_in[7];
    const float* Wo  = (const float*)d_in[8];
    const float* bj  = (const float*)d_in[9];
    const float* bi_ = (const float*)d_in[10];
    const float* bf  = (const float*)d_in[11];
    const float* bo  = (const float*)d_in[12];
    const float* Fa  = (const float*)d_in[13];
    const float* Fab = (const float*)d_in[14];
    const float* Fbw = (const float*)d_in[15];
    const float* Fbb = (const float*)d_in[16];
    const float* Pw  = (const float*)d_in[17];
    const float* Pb  = (const float*)d_in[18];
    float* out = (float*)d_out;

    size_t smem = SMTOT * sizeof(float);  // ~68 KB
    cudaFuncSetAttribute(lstm_kernel, cudaFuncAttributeMaxDynamicSharedMemorySize, (int)smem);

    lstm_kernel<<<dim3(32, 4), 512, smem>>>(x, Uj, Ui_, Uf, Uo, Wj, Wi_, Wf, Wo,
                                            bj, bi_, bf, bo, Fa, Fab);
    alpha_kernel<<<4096, 256>>>(out);
    head_kernel<<<128, 32>>>(out, Pw, Pb, Fbw, Fbb);
}

// round 10
// speedup vs baseline: 3.7104x; 1.6005x over previous
#include <cuda_runtime.h>

// Problem constants
#define B_DIM 128
#define T_DIM 256
#define D_DIM 32
#define N_DIM 64

// Scratch (device globals: no allocation allowed)
__device__ float g_aBuf[D_DIM * T_DIM * B_DIM];   // [i][t][b] unnormalized alphas
__device__ float g_denBuf[D_DIM * B_DIM];         // [i][b]
__device__ float g_gBuf[B_DIM * D_DIM * N_DIM];   // [b][i][k] g_n (normalized)
__device__ float g_hTBuf[B_DIM * D_DIM * N_DIM];  // [b][i][k] h_T

// ---------------- math helpers ----------------
static __device__ __forceinline__ float tanha(float x) {
    float y;
    asm("tanh.approx.f32 %0, %1;" : "=f"(y) : "f"(x));
    return y;
}
static __device__ __forceinline__ float siga(float x) {
    return fmaf(tanha(0.5f * x), 0.5f, 0.5f);
}
static __device__ __forceinline__ unsigned cvt_tf32(float x) {
    unsigned r;
    asm("cvt.rna.tf32.f32 %0, %1;" : "=r"(r) : "f"(x));
    return r;
}
// m16n8k8 tf32 MMA, C += A*B  (A row-major frag, B col-major frag)
static __device__ __forceinline__ void mma8(float* C,
                                            unsigned a0, unsigned a1,
                                            unsigned a2, unsigned a3,
                                            unsigned b0, unsigned b1) {
    asm("mma.sync.aligned.m16n8k8.row.col.f32.tf32.tf32.f32 "
        "{%0,%1,%2,%3}, {%4,%5,%6,%7}, {%8,%9}, {%0,%1,%2,%3};"
        : "+f"(C[0]), "+f"(C[1]), "+f"(C[2]), "+f"(C[3])
        : "r"(a0), "r"(a1), "r"(a2), "r"(a3), "r"(b0), "r"(b1));
}
#define GBAR(gid) asm volatile("bar.sync %0, 256;" :: "r"((gid) + 1) : "memory")

// ---------------- shared memory layout (float offsets) ----------------
// x: [t][32 b].  h per group: 2 buffers x [16 rows][stride 68] single tf32 floats.
// sp per group: 2 buffers (t&1) x [8 w][16 b].
#define XS   0       // 8192
#define HBF  8192    // 2 groups * 2 * 1088 = 4352
#define SPF  12544   // 2 groups * 2 * 128 = 512
#define INVF 13056   // 2 * 16 = 32
#define SMTOT 13088  // floats -> 52352 bytes

// ===================== Kernel 1: fused LSTM via single-pass TF32 mma.sync =====================
// grid = (32 i, 4 b-chunks), block = 512 = 2 groups x 8 warps; ONE barrier per step.
// Group gid handles b rows [16*gid, 16*gid+16) (M=16).
// Warp wg owns k in [8wg, 8wg+8): nt0=k(0..3)x(j,i), nt1=k(0..3)x(f,o),
//                                 nt2=k(4..7)x(j,i), nt3=k(4..7)x(f,o).
// Lane (g=lane>>2, t4=lane&3): C cells = b rows {g, g+8} x k {8wg+t4, 8wg+4+t4} x 4 gates.
__global__ void __launch_bounds__(512, 1)
lstm_kernel(const float* __restrict__ x,
            const float* __restrict__ Uj, const float* __restrict__ Ui_,
            const float* __restrict__ Uf, const float* __restrict__ Uo,
            const float* __restrict__ Wj, const float* __restrict__ Wi_,
            const float* __restrict__ Wf, const float* __restrict__ Wo,
            const float* __restrict__ bj, const float* __restrict__ bi_,
            const float* __restrict__ bf, const float* __restrict__ bo,
            const float* __restrict__ Fa, const float* __restrict__ Fab) {
    extern __shared__ float sm[];
    const int tid  = threadIdx.x;
    const int gid  = tid >> 8;            // group 0/1
    const int wg   = (tid >> 5) & 7;      // warp in group
    const int lane = tid & 31;
    const int g    = lane >> 2;
    const int t4   = lane & 3;
    const int bl   = lane & 15;           // b-row for alpha compute
    const int i    = blockIdx.x;
    const int b0g  = (blockIdx.y << 5) + (gid << 4);

    // ---- cooperative smem init (full CTA) ----
    for (int idx = tid; idx < 4352; idx += 512) sm[HBF + idx] = 0.0f;
    {
        const int cb0 = blockIdx.y << 5;
        for (int idx = tid; idx < 8192; idx += 512) {
            int tt = idx >> 5, blx = idx & 31;
            sm[XS + idx] = x[((cb0 + blx) * 256 + tt) * 32 + i];
        }
    }

    // ---- stationary B (weight) fragments, tf32 (exact truncation of W) ----
    unsigned Bhi[8][4][2];
    {
        const float* WgP[4] = {Wj, Wi_, Wf, Wo};
#pragma unroll
        for (int kt = 0; kt < 8; kt++)
#pragma unroll
            for (int nt = 0; nt < 4; nt++) {
                int kB = 8 * wg + ((nt >> 1) << 2) + (g >> 1);
                const float* Wp = WgP[((nt & 1) << 1) + (g & 1)];
#pragma unroll
                for (int r = 0; r < 2; r++) {
                    int j = kt * 8 + t4 + 4 * r;
                    Bhi[kt][nt][r] = cvt_tf32(Wp[(j * 32 + i) * 64 + kB]);
                }
            }
    }

    // ---- per-lane constants: 2 k-values x 4 gates ----
    float Uv[2][4], Bv[2][4], fav[2];
    {
        const float* Ug[4] = {Uj, Ui_, Uf, Uo};
        const float* Bg[4] = {bj, bi_, bf, bo};
#pragma unroll
        for (int ka = 0; ka < 2; ka++) {
            int kk = 8 * wg + 4 * ka + t4;
#pragma unroll
            for (int gg = 0; gg < 4; gg++) {
                Uv[ka][gg] = Ug[gg][i * 64 + kk];
                Bv[ka][gg] = Bg[gg][i * 64 + kk];
            }
            fav[ka] = Fa[kk * 32 + i];
        }
    }
    const float FabV = Fab[i];

    // ---- state ----
    float cst[2][2], gacc[2][2], hn[2][2];
#pragma unroll
    for (int ka = 0; ka < 2; ka++)
#pragma unroll
        for (int bh = 0; bh < 2; bh++) {
            cst[ka][bh] = 0.0f; gacc[ka][bh] = 0.0f; hn[ka][bh] = 0.0f;
        }
    float den = 0.0f;  // per-lane, b = bl (redundant across warps)

    __syncthreads();
    int cur = 0;
    const int hbase  = HBF + gid * 2176;
    const int spbase = SPF + gid * 256;
    const int xb0    = (gid << 4) + g;

    for (int t = 0; t < 256; t++) {
        // ---- C init = bias + x*U ----
        const float xv0 = sm[XS + t * 32 + xb0];
        const float xv1 = sm[XS + t * 32 + xb0 + 8];
        float C[4][4];
#pragma unroll
        for (int nt = 0; nt < 4; nt++)
#pragma unroll
            for (int r = 0; r < 4; r++) {
                int gate = ((nt & 1) << 1) + (r & 1);
                int ka = nt >> 1;
                C[nt][r] = fmaf((r >> 1) ? xv1 : xv0, Uv[ka][gate], Bv[ka][gate]);
            }

        // ---- MMA: C += A_hi * B  (single tf32 pass) ----
        const float* hb = sm + hbase + cur * 1088;
#pragma unroll
        for (int kt = 0; kt < 8; kt++) {
            int c0 = kt * 8 + t4;
            unsigned a0 = __float_as_uint(hb[g * 68 + c0]);
            unsigned a1 = __float_as_uint(hb[(g + 8) * 68 + c0]);
            unsigned a2 = __float_as_uint(hb[g * 68 + c0 + 4]);
            unsigned a3 = __float_as_uint(hb[(g + 8) * 68 + c0 + 4]);
#pragma unroll
            for (int nt = 0; nt < 4; nt++)
                mma8(C[nt], a0, a1, a2, a3, Bhi[kt][nt][0], Bhi[kt][nt][1]);
        }

        // ---- activations + state update + alpha partials ----
        float sp0 = 0.0f, sp1 = 0.0f;
#pragma unroll
        for (int ka = 0; ka < 2; ka++)
#pragma unroll
            for (int bh = 0; bh < 2; bh++) {
                int rb = bh << 1;
                float jj = tanha(C[2 * ka][rb]);
                float ii = siga(C[2 * ka][rb + 1]);
                float ff = siga(C[2 * ka + 1][rb]);
                float oo = siga(C[2 * ka + 1][rb + 1]);
                float cn = fmaf(cst[ka][bh], ff, ii * jj);
                cst[ka][bh] = cn;
                float hv = oo * tanha(cn);
                hn[ka][bh] = hv;
                if (bh == 0) sp0 = fmaf(hv, fav[ka], sp0);
                else         sp1 = fmaf(hv, fav[ka], sp1);
            }
        sp0 += __shfl_xor_sync(0xffffffffu, sp0, 1);
        sp0 += __shfl_xor_sync(0xffffffffu, sp0, 2);
        sp1 += __shfl_xor_sync(0xffffffffu, sp1, 1);
        sp1 += __shfl_xor_sync(0xffffffffu, sp1, 2);
        const int spb = spbase + (t & 1) * 128;
        if (t4 == 0) {
            sm[spb + wg * 16 + g]     = sp0;
            sm[spb + wg * 16 + g + 8] = sp1;
        }

        // ---- write h(t) as tf32-rounded floats to ping-pong buffer ----
        float* hw = sm + hbase + (cur ^ 1) * 1088;
#pragma unroll
        for (int ka = 0; ka < 2; ka++) {
            int kk = 8 * wg + 4 * ka + t4;
#pragma unroll
            for (int bh = 0; bh < 2; bh++)
                hw[(g + 8 * bh) * 68 + kk] =
                    __uint_as_float(cvt_tf32(hn[ka][bh]));
        }

        GBAR(gid);  // ONE barrier per step: sp(t) + h(t) visible within group

        // ---- alpha(t): computed redundantly by every warp (fully parallel) ----
        {
            const float* spp = sm + spb;
            float sA = FabV, sB = 0.0f;
#pragma unroll
            for (int ww = 0; ww < 8; ww += 2) {
                sA += spp[ww * 16 + bl];
                sB += spp[(ww + 1) * 16 + bl];
            }
            float av = __expf(tanha(sA + sB));
            den += av;
            float av0 = __shfl_sync(0xffffffffu, av, g);
            float av1 = __shfl_sync(0xffffffffu, av, g + 8);
#pragma unroll
            for (int ka = 0; ka < 2; ka++) {
                gacc[ka][0] = fmaf(av0, hn[ka][0], gacc[ka][0]);
                gacc[ka][1] = fmaf(av1, hn[ka][1], gacc[ka][1]);
            }
            if (wg == 0 && lane < 16)
                g_aBuf[(i * 256 + t) * 128 + b0g + lane] = av;
        }

        cur ^= 1;
    }

    // ---- finalize denominators ----
    if (wg == 0 && lane < 16) {
        sm[INVF + gid * 16 + lane] = __fdividef(1.0f, den);
        g_denBuf[i * 128 + b0g + lane] = den;
    }
    GBAR(gid);

    // ---- epilogue: write g_n and h_T ----
    {
        float inv0 = sm[INVF + gid * 16 + g];
        float inv1 = sm[INVF + gid * 16 + g + 8];
#pragma unroll
        for (int ka = 0; ka < 2; ka++) {
            int kk = 8 * wg + 4 * ka + t4;
            int bg0 = b0g + g, bg1 = b0g + g + 8;
            g_gBuf[(bg0 * 32 + i) * 64 + kk]  = gacc[ka][0] * inv0;
            g_gBuf[(bg1 * 32 + i) * 64 + kk]  = gacc[ka][1] * inv1;
            g_hTBuf[(bg0 * 32 + i) * 64 + kk] = hn[ka][0];
            g_hTBuf[(bg1 * 32 + i) * 64 + kk] = hn[ka][1];
        }
    }
}

// ===================== Kernel 2: normalize alphas into [B,T,D] =====================
__global__ void alpha_kernel(float* __restrict__ out) {
    int idx = blockIdx.x * 256 + threadIdx.x;  // 0 .. 1048575
    int b = idx >> 13;
    int r = idx & 8191;
    int t = r >> 5;
    int i = r & 31;
    float a = g_aBuf[(i * 256 + t) * 128 + b];
    float d = g_denBuf[i * 128 + b];
    out[128 + idx] = __fdividef(a, d);
}

// ===================== Kernel 3: output head =====================
__global__ void head_kernel(float* __restrict__ out,
                            const float* __restrict__ Phi_w, const float* __restrict__ Phi_b,
                            const float* __restrict__ Fbw, const float* __restrict__ Fbb) {
    int b = blockIdx.x;
    int i = threadIdx.x;
    const float* gp = g_gBuf + (b * 32 + i) * 64;
    const float* hp = g_hTBuf + (b * 32 + i) * 64;
    float mu = Phi_b[0];
    float bs = Fbb[0];
#pragma unroll 8
    for (int kk = 0; kk < 64; kk++) {
        float gv = gp[kk], hv = hp[kk];
        mu = fmaf(gv, Phi_w[kk], mu);
        mu = fmaf(hv, Phi_w[64 + kk], mu);
        bs = fmaf(gv, Fbw[kk], bs);
        bs = fmaf(hv, Fbw[64 + kk], bs);
    }
    float e = __expf(tanha(bs));
    float se = e, sem = e * mu;
#pragma unroll
    for (int off = 16; off; off >>= 1) {
        se  += __shfl_xor_sync(0xffffffffu, se, off);
        sem += __shfl_xor_sync(0xffffffffu, sem, off);
    }
    out[128 + 1048576 + b * 32 + i] = __fdividef(e, se);  // betas
    if (i == 0) out[b] = __fdividef(sem, se);             // mean
}

// ===================== launch =====================
extern "C" void kernel_launch(void* const* d_in, const int* in_sizes, int n_in,
                              void* d_out, int out_size) {
    const float* x   = (const float*)d_in[0];
    const float* Uj  = (const float*)d_in[1];
    const float* Ui_ = (const float*)d_in[2];
    const float* Uf  = (const float*)d_in[3];
    const float* Uo  = (const float*)d_in[4];
    const float* Wj  = (const float*)d_in[5];
    const float* Wi_ = (const float*)d_in[6];
    const float* Wf  = (const float*)d_in[7];
    const float* Wo  = (const float*)d_in[8];
    const float* bj  = (const float*)d_in[9];
    const float* bi_ = (const float*)d_in[10];
    const float* bf  = (const float*)d_in[11];
    const float* bo  = (const float*)d_in[12];
    const float* Fa  = (const float*)d_in[13];
    const float* Fab = (const float*)d_in[14];
    const float* Fbw = (const float*)d_in[15];
    const float* Fbb = (const float*)d_in[16];
    const float* Pw  = (const float*)d_in[17];
    const float* Pb  = (const float*)d_in[18];
    float* out = (float*)d_out;

    size_t smem = SMTOT * sizeof(float);  // ~52 KB
    cudaFuncSetAttribute(lstm_kernel, cudaFuncAttributeMaxDynamicSharedMemorySize, (int)smem);

    lstm_kernel<<<dim3(32, 4), 512, smem>>>(x, Uj, Ui_, Uf, Uo, Wj, Wi_, Wf, Wo,
                                            bj, bi_, bf, bo, Fa, Fab);
    alpha_kernel<<<4096, 256>>>(out);
    head_kernel<<<128, 32>>>(out, Pw, Pb, Fbw, Fbb);
}